// round 4
// baseline (speedup 1.0000x reference)
#include <cuda_runtime.h>

#define NS   16
#define NP   2048
#define DIMS 64
#define KK   16
#define BLK  128     // threads per block == queries per block
#define TJ   128     // candidate tile size
#define TOT  (NS*NP*KK)

__device__ float g_x2[NS * NP];

// ---------- row squared norms ----------
__global__ void x2_kernel(const float* __restrict__ h) {
    int r = blockIdx.x * blockDim.x + threadIdx.x;
    if (r >= NS * NP) return;
    const float4* p = (const float4*)(h + (size_t)r * DIMS);
    float s = 0.f;
#pragma unroll
    for (int t = 0; t < DIMS / 4; t++) {
        float4 v = p[t];
        s += v.x * v.x + v.y * v.y + v.z * v.z + v.w * v.w;
    }
    g_x2[r] = s;
}

// ---------- packed f32x2 helpers ----------
__device__ __forceinline__ unsigned long long pack2(float x) {
    unsigned long long r;
    asm("mov.b64 %0, {%1, %1};" : "=l"(r) : "f"(x));
    return r;
}
__device__ __forceinline__ void ffma2(unsigned long long& d,
                                      unsigned long long a,
                                      unsigned long long b) {
    asm("fma.rn.f32x2 %0, %1, %2, %0;" : "+l"(d) : "l"(a), "l"(b));
}
__device__ __forceinline__ float2 unpack2(unsigned long long v) {
    float2 f;
    asm("mov.b64 {%0, %1}, %2;" : "=f"(f.x), "=f"(f.y) : "l"(v));
    return f;
}

// ---------- sorted register top-K (stable, strict <) ----------
__device__ __forceinline__ void topk_insert(float (&kd)[KK], int (&ki)[KK],
                                            float d, int j) {
    kd[KK - 1] = d;
    ki[KK - 1] = j;
#pragma unroll
    for (int t = KK - 1; t > 0; t--) {
        if (kd[t] < kd[t - 1]) {
            float td = kd[t]; kd[t] = kd[t - 1]; kd[t - 1] = td;
            int   ti = ki[t]; ki[t] = ki[t - 1]; ki[t - 1] = ti;
        }
    }
}

__global__ __launch_bounds__(BLK) void knn_kernel(const float* __restrict__ h,
                                                  float* __restrict__ out) {
    __shared__ float sh[DIMS][TJ];   // transposed candidate tile: sh[d][j]
    __shared__ float shx2[TJ];

    const int b   = blockIdx.y;
    const int tid = threadIdx.x;
    const int i   = blockIdx.x * BLK + tid;

    // query vector in registers
    float q[DIMS];
    {
        const float4* hq = (const float4*)(h + ((size_t)b * NP + i) * DIMS);
#pragma unroll
        for (int t = 0; t < DIMS / 4; t++) {
            float4 v = hq[t];
            q[4 * t + 0] = v.x; q[4 * t + 1] = v.y;
            q[4 * t + 2] = v.z; q[4 * t + 3] = v.w;
        }
    }
    const float qx2 = g_x2[b * NP + i];

    float kd[KK];
    int   ki[KK];
#pragma unroll
    for (int k = 0; k < KK; k++) { kd[k] = __int_as_float(0x7f800000); ki[k] = 0; }

#pragma unroll 1
    for (int j0 = 0; j0 < NP; j0 += TJ) {
        __syncthreads();
        // cooperatively stage TJ candidate rows, transposed
        {
            const float4* hr =
                (const float4*)(h + ((size_t)b * NP + j0 + tid) * DIMS);
#pragma unroll
            for (int t = 0; t < DIMS / 4; t++) {
                float4 v = hr[t];
                sh[4 * t + 0][tid] = v.x;
                sh[4 * t + 1][tid] = v.y;
                sh[4 * t + 2][tid] = v.z;
                sh[4 * t + 3][tid] = v.w;
            }
            shx2[tid] = g_x2[b * NP + j0 + tid];
        }
        __syncthreads();

#pragma unroll 1
        for (int js = 0; js < TJ; js += 16) {
            unsigned long long acc[8];
#pragma unroll
            for (int p = 0; p < 8; p++) acc[p] = 0ull;

#pragma unroll
            for (int d = 0; d < DIMS; d++) {
                unsigned long long q2 = pack2(q[d]);
                const ulonglong2* srow = (const ulonglong2*)&sh[d][js];
#pragma unroll
                for (int p = 0; p < 4; p++) {
                    ulonglong2 sv = srow[p];   // broadcast LDS.128
                    ffma2(acc[2 * p + 0], q2, sv.x);
                    ffma2(acc[2 * p + 1], q2, sv.y);
                }
            }

#pragma unroll
            for (int p = 0; p < 8; p++) {
                float2 dot = unpack2(acc[p]);
                int    j   = j0 + js + 2 * p;
                float  d0  = fmaf(-2.f, dot.x, qx2 + shx2[js + 2 * p + 0]);
                float  d1  = fmaf(-2.f, dot.y, qx2 + shx2[js + 2 * p + 1]);
                if (d0 < kd[KK - 1]) topk_insert(kd, ki, d0, j);
                if (d1 < kd[KK - 1]) topk_insert(kd, ki, d1, j + 1);
            }
        }
    }

    // write outputs: [knn_dist | dst | src], indices as float values
    const size_t base = ((size_t)b * NP + i) * KK;
    const int    goff = b * NP;
#pragma unroll
    for (int k = 0; k < KK; k++) {
        out[base + k]                     = kd[k];
        out[(size_t)TOT + base + k]       = (float)(ki[k] + goff);
        out[2 * (size_t)TOT + base + k]   = (float)(i + goff);
    }
}

extern "C" void kernel_launch(void* const* d_in, const int* in_sizes, int n_in,
                              void* d_out, int out_size) {
    const float* h = (const float*)d_in[0];
    (void)in_sizes; (void)n_in; (void)out_size;  // K is fixed at 16

    x2_kernel<<<(NS * NP + 255) / 256, 256>>>(h);

    dim3 grid(NP / BLK, NS);
    knn_kernel<<<grid, BLK>>>(h, (float*)d_out);
}